// round 9
// baseline (speedup 1.0000x reference)
#include <cuda_runtime.h>
#include <cstdint>

// ---------------------------------------------------------------------------
// NeuralMinSumDecoder — banded Tanner graph (A=48271, A^-1=57967 mod 2^16).
// Base b touches checks b..b+5; check c touches bases c-5..c, halves h=0/1.
// One thread per slot handling BOTH halves as float2. KK iterations fused per
// launch; betas staged via smem with register prefetch; tree-structured
// top-2/argmin; parity-XOR sign application; deferred per-iteration syndrome
// reduced at launch end via KK boolean __syncthreads_or calls.
// ---------------------------------------------------------------------------

#define MCC   65536
#define NVV   131072
#define TMAXX 30
#define EDG   (NVV * 6)
#define MC6   (MCC * 6)
#define AINV  57967u
#define MMSK  0xFFFFu

#define NB    128                 // owned bases/checks per block
#define KK    3                   // iterations per launch
#define HL    20                  // left halo (5*KK + 5 for syndrome)
#define HR    15                  // right halo (5*KK)
#define WW    (NB + HL + HR)      // 163 slots
#define THR   192                 // one thread per slot (warp multiple)
#define GRD   (MCC / NB)          // 512 blocks
#define NLAUNCH (TMAXX / KK)      // 10
#define ST    13                  // smem row stride in float2 (conflict-free)

__device__ __align__(16) float2 g_v2c[2][MC6];  // [buf][c*6+l] = (h0,h1)
__device__ float2 g_llr2[MCC];                  // (llr[r], llr[r+M]) by base b
__device__ float2 g_post[MCC];                  // posterior pair by base b
__device__ int    g_synflag[TMAXX];             // 0 => syndrome all-zero at t

// ---------------------------------------------------------------------------
__global__ void k_init(const float* __restrict__ llr) {
    unsigned c = blockIdx.x * blockDim.x + threadIdx.x;   // 0..MC-1
    unsigned r = (AINV * c) & MMSK;
    g_llr2[c] = make_float2(llr[r], llr[r + MCC]);
#pragma unroll
    for (int l = 0; l < 6; l++) {
        unsigned rl = (AINV * (c - (unsigned)l)) & MMSK;
        g_v2c[0][c * 6 + l] = make_float2(llr[rl], llr[rl + MCC]);
    }
    if (c < TMAXX) g_synflag[c] = 0;
}

// ---------------------------------------------------------------------------
__global__ __launch_bounds__(THR, 5) void k_fused(
        const float* __restrict__ betas, int t0, int rbuf) {
    __shared__ float2 s_msg[WW * ST];            // v2c / c2v, in place
    __shared__ float2 s_beta[(WW + 5) * ST];     // 5-row front pad
    __shared__ unsigned char sp[KK][NB + 6];
    __shared__ int s_frozen;

    int tid = threadIdx.x;
    if (tid == 0) {
        int f = 0;
        for (int tt = 0; tt < t0; tt++) f |= (g_synflag[tt] == 0);
        s_frozen = f;
    }
    __syncthreads();
    if (s_frozen) return;

    bool act = tid < WW;
    int  s   = act ? tid : WW - 1;
    unsigned B0 = blockIdx.x * NB;
    unsigned c  = (B0 - (unsigned)HL + (unsigned)s) & MMSK;

    int eidA[6];                          // edge id (== beta offset), h=0
#pragma unroll
    for (int l = 0; l < 6; l++) {
        unsigned rl = (AINV * (c - (unsigned)l)) & MMSK;
        eidA[l] = (int)(rl * 6u + (unsigned)l);
    }
    float2 llr = g_llr2[c];

    // load v2c row (3x LDG.128, coalesced) into own smem row
    const float4* gv = (const float4*)&g_v2c[rbuf][c * 6];
    float4 q0 = gv[0], q1 = gv[1], q2 = gv[2];
    if (act) {
        s_msg[s * ST + 0] = make_float2(q0.x, q0.y);
        s_msg[s * ST + 1] = make_float2(q0.z, q0.w);
        s_msg[s * ST + 2] = make_float2(q1.x, q1.y);
        s_msg[s * ST + 3] = make_float2(q1.z, q1.w);
        s_msg[s * ST + 4] = make_float2(q2.x, q2.y);
        s_msg[s * ST + 5] = make_float2(q2.z, q2.w);
    }
    if (tid < 5) {                                // zero beta pad rows
#pragma unroll
        for (int l = 0; l < 6; l++)
            s_beta[tid * ST + l] = make_float2(0.0f, 0.0f);
    }

    // beta rows for own base (contiguous 24B each, h=0 and h=1)
    const float* pr0 = betas + (size_t)t0 * EDG + eidA[0];
    const float* pr1 = pr0 + MC6;
    float2 a0, a1, a2, b0, b1, b2;
    if (act) {
        a0 = *(const float2*)(pr0 + 0);
        a1 = *(const float2*)(pr0 + 2);
        a2 = *(const float2*)(pr0 + 4);
        b0 = *(const float2*)(pr1 + 0);
        b1 = *(const float2*)(pr1 + 2);
        b2 = *(const float2*)(pr1 + 4);
    }
    float2* gdst = g_v2c[rbuf ^ 1];
    const float INF = __int_as_float(0x7f800000);

#pragma unroll
    for (int k = 1; k <= KK; k++) {
        // stage current betas; prefetch next iteration's rows
        if (act) {
            float2* br = &s_beta[(s + 5) * ST];
            br[0] = make_float2(a0.x, b0.x);
            br[1] = make_float2(a0.y, b0.y);
            br[2] = make_float2(a1.x, b1.x);
            br[3] = make_float2(a1.y, b1.y);
            br[4] = make_float2(a2.x, b2.x);
            br[5] = make_float2(a2.y, b2.y);
            if (k < KK) {
                pr0 += EDG; pr1 += EDG;
                a0 = *(const float2*)(pr0 + 0);
                a1 = *(const float2*)(pr0 + 2);
                a2 = *(const float2*)(pr0 + 4);
                b0 = *(const float2*)(pr1 + 0);
                b1 = *(const float2*)(pr1 + 2);
                b2 = *(const float2*)(pr1 + 4);
            }
        }
        __syncthreads();

        // ---- check phase: own row (12 edges in-thread) ----
        float2 v[6];
#pragma unroll
        for (int l = 0; l < 6; l++) v[l] = s_msg[s * ST + l];

        float mg[12];
        unsigned allx = 0u;
#pragma unroll
        for (int l = 0; l < 6; l++) {
            mg[2 * l]     = fabsf(v[l].x);
            mg[2 * l + 1] = fabsf(v[l].y);
            allx ^= __float_as_uint(v[l].x) ^ __float_as_uint(v[l].y);
        }
        // m1: fmin tree
        float p6[6];
#pragma unroll
        for (int i = 0; i < 6; i++) p6[i] = fminf(mg[2 * i], mg[2 * i + 1]);
        float m1 = fminf(fminf(fminf(p6[0], p6[1]), fminf(p6[2], p6[3])),
                         fminf(p6[4], p6[5]));
        // e1: min edge id among mags == m1 (tree)
        int cnd[12];
#pragma unroll
        for (int l = 0; l < 6; l++) {
            cnd[2 * l]     = (mg[2 * l]     == m1) ? eidA[l]       : 0x7fffffff;
            cnd[2 * l + 1] = (mg[2 * l + 1] == m1) ? eidA[l] + MC6 : 0x7fffffff;
        }
        int c6[6];
#pragma unroll
        for (int i = 0; i < 6; i++) c6[i] = min(cnd[2 * i], cnd[2 * i + 1]);
        int e1 = min(min(min(c6[0], c6[1]), min(c6[2], c6[3])),
                     min(c6[4], c6[5]));
        // m2: fmin tree excluding edge e1
        float ex[12];
#pragma unroll
        for (int l = 0; l < 6; l++) {
            ex[2 * l]     = (eidA[l]       == e1) ? INF : mg[2 * l];
            ex[2 * l + 1] = (eidA[l] + MC6 == e1) ? INF : mg[2 * l + 1];
        }
        float x6[6];
#pragma unroll
        for (int i = 0; i < 6; i++) x6[i] = fminf(ex[2 * i], ex[2 * i + 1]);
        float m2 = fminf(fminf(fminf(x6[0], x6[1]), fminf(x6[2], x6[3])),
                         fminf(x6[4], x6[5]));

        // outputs: sign via parity XOR on bit 31
#pragma unroll
        for (int l = 0; l < 6; l++) {
            float2 bb = s_beta[(s - l + 5) * ST + l];   // diag, conflict-free
            float selA = (eidA[l]       == e1) ? m2 : m1;
            float selB = (eidA[l] + MC6 == e1) ? m2 : m1;
            unsigned fA = (allx ^ __float_as_uint(v[l].x)) & 0x80000000u;
            unsigned fB = (allx ^ __float_as_uint(v[l].y)) & 0x80000000u;
            float oA = __uint_as_float(__float_as_uint(bb.x * selA) ^ fA);
            float oB = __uint_as_float(__float_as_uint(bb.y * selB) ^ fB);
            if (act) s_msg[s * ST + l] = make_float2(oA, oB);  // c2v in place
        }
        __syncthreads();

        // ---- variable phase: diagonal (unique producer/consumer per elem) ----
        bool actv = tid < WW - 5;
        int  x    = actv ? tid : 0;
        float2 cv[6];
        float s0 = 0.0f, s1 = 0.0f;
#pragma unroll
        for (int l = 0; l < 6; l++) {
            cv[l] = s_msg[(x + l) * ST + l];
            s0 += cv[l].x; s1 += cv[l].y;
        }
        float tp0 = llr.x + s0;
        float tp1 = llr.y + s1;

        if (k < KK) {
            if (actv) {
#pragma unroll
                for (int l = 0; l < 6; l++)
                    s_msg[(x + l) * ST + l] =
                        make_float2(tp0 - cv[l].x, tp1 - cv[l].y);
            }
        } else if (tid >= HL && tid < HL + NB) {      // owned writeback
#pragma unroll
            for (int l = 0; l < 6; l++)
                gdst[(int)(((c + (unsigned)l) & MMSK) * 6u + (unsigned)l)] =
                    make_float2(tp0 - cv[l].x, tp1 - cv[l].y);
            g_post[c] = make_float2(tp0, tp1);
        }
        if (tid >= HL - 5 && tid < HL + NB)
            sp[k - 1][tid - (HL - 5)] =
                (unsigned char)(((tp0 < 0.0f) ? 1 : 0) ^ ((tp1 < 0.0f) ? 1 : 0));
        // published by next iteration's first barrier / the final barrier
    }

    // ---- deferred syndrome reduce: boolean __syncthreads_or per iteration ----
    __syncthreads();
    int bits[KK];
#pragma unroll
    for (int k = 0; k < KK; k++) {
        bits[k] = 0;
        if (tid < NB)
            bits[k] = sp[k][tid] ^ sp[k][tid + 1] ^ sp[k][tid + 2] ^
                      sp[k][tid + 3] ^ sp[k][tid + 4] ^ sp[k][tid + 5];
    }
#pragma unroll
    for (int k = 0; k < KK; k++) {
        int odd = __syncthreads_or(bits[k]);     // boolean reduce (guaranteed)
        if (odd && tid == 0) g_synflag[t0 + k] = 1;   // benign same-value race
    }
}

// ---------------------------------------------------------------------------
__global__ void k_out(float* __restrict__ out, int out_size) {
    unsigned b = blockIdx.x * blockDim.x + threadIdx.x;   // base 0..MC-1
    float2 P = g_post[b];
    unsigned r = (AINV * b) & MMSK;

    if ((int)r < out_size)               out[r]             = (P.x < 0.0f) ? 1.0f : 0.0f;
    if ((int)(r + MCC) < out_size)       out[r + MCC]       = (P.y < 0.0f) ? 1.0f : 0.0f;
    if ((int)(NVV + r) < out_size)       out[NVV + r]       = P.x;
    if ((int)(NVV + r + MCC) < out_size) out[NVV + r + MCC] = P.y;

    if (b == 0 && 2 * NVV < out_size) {
        int iters = TMAXX;
        for (int tt = 0; tt < TMAXX; tt++)
            if (g_synflag[tt] == 0) { iters = tt + 1; break; }
        out[2 * NVV] = (float)iters;
    }
}

// ---------------------------------------------------------------------------
extern "C" void kernel_launch(void* const* d_in, const int* in_sizes, int n_in,
                              void* d_out, int out_size) {
    const float* llr   = (const float*)d_in[0];
    const float* betas = (const float*)d_in[1];
    (void)in_sizes; (void)n_in;

    k_init<<<MCC / 256, 256>>>(llr);
    for (int g = 0; g < NLAUNCH; g++)
        k_fused<<<GRD, THR>>>(betas, g * KK, g & 1);
    k_out<<<MCC / 256, 256>>>((float*)d_out, out_size);
}

// round 10
// speedup vs baseline: 1.6366x; 1.6366x over previous
#include <cuda_runtime.h>
#include <cstdint>

// ---------------------------------------------------------------------------
// NeuralMinSumDecoder — banded Tanner graph (A=48271, A^-1=57967 mod 2^16).
// Base b touches checks b..b+5; check c touches bases c-5..c, halves h=0/1.
// One thread per slot handling BOTH halves as float2. KK=5 iterations fused
// per launch (trapezoid halo); betas staged via smem with register prefetch;
// serial top-2 (proven fastest); parity-XOR sign application.
// ---------------------------------------------------------------------------

#define MCC   65536
#define NVV   131072
#define TMAXX 30
#define EDG   (NVV * 6)
#define MC6   (MCC * 6)
#define AINV  57967u
#define MMSK  0xFFFFu

#define NB    128                 // owned bases/checks per block
#define KK    5                   // iterations per launch
#define HL    (5 * KK + 5)        // 30 (extra 5 for syndrome halo)
#define HR    (5 * KK)            // 25
#define WW    (NB + HL + HR)      // 183 slots
#define THR   192                 // one thread per slot (warp multiple)
#define GRD   (MCC / NB)          // 512 blocks
#define NLAUNCH (TMAXX / KK)      // 6
#define ST    13                  // smem row stride in float2 (conflict-free)

__device__ __align__(16) float2 g_v2c[2][MC6];  // [buf][c*6+l] = (h0,h1)
__device__ float2 g_llr2[MCC];                  // (llr[r], llr[r+M]) by base b
__device__ float2 g_post[MCC];                  // posterior pair by base b
__device__ int    g_synflag[TMAXX];             // 0 => syndrome all-zero at t

// ---------------------------------------------------------------------------
__global__ void k_init(const float* __restrict__ llr) {
    unsigned c = blockIdx.x * blockDim.x + threadIdx.x;   // 0..MC-1
    unsigned r = (AINV * c) & MMSK;
    g_llr2[c] = make_float2(llr[r], llr[r + MCC]);
#pragma unroll
    for (int l = 0; l < 6; l++) {
        unsigned rl = (AINV * (c - (unsigned)l)) & MMSK;
        g_v2c[0][c * 6 + l] = make_float2(llr[rl], llr[rl + MCC]);
    }
    if (c < TMAXX) g_synflag[c] = 0;
}

// ---------------------------------------------------------------------------
__global__ __launch_bounds__(THR, 4) void k_fused(
        const float* __restrict__ betas, int t0, int rbuf) {
    __shared__ float2 s_msg[WW * ST];            // v2c / c2v, in place
    __shared__ float2 s_beta[(WW + 5) * ST];     // 5-row front pad
    __shared__ unsigned char sp[NB + 6];
    int tid = threadIdx.x;

    // frozen check: one flag per thread, boolean or-reduce
    int myf = (tid < t0) ? (g_synflag[tid] == 0) : 0;
    if (__syncthreads_or(myf)) return;

    bool act = tid < WW;
    int  s   = act ? tid : WW - 1;
    unsigned B0 = blockIdx.x * NB;
    unsigned c  = (B0 - (unsigned)HL + (unsigned)s) & MMSK;

    int eidA[6];                          // edge id (== beta offset), h=0
#pragma unroll
    for (int l = 0; l < 6; l++) {
        unsigned rl = (AINV * (c - (unsigned)l)) & MMSK;
        eidA[l] = (int)(rl * 6u + (unsigned)l);
    }
    float2 llr = g_llr2[c];

    // load v2c row (3x LDG.128, coalesced) into own smem row
    const float4* gv = (const float4*)&g_v2c[rbuf][c * 6];
    float4 q0 = gv[0], q1 = gv[1], q2 = gv[2];
    if (act) {
        s_msg[s * ST + 0] = make_float2(q0.x, q0.y);
        s_msg[s * ST + 1] = make_float2(q0.z, q0.w);
        s_msg[s * ST + 2] = make_float2(q1.x, q1.y);
        s_msg[s * ST + 3] = make_float2(q1.z, q1.w);
        s_msg[s * ST + 4] = make_float2(q2.x, q2.y);
        s_msg[s * ST + 5] = make_float2(q2.z, q2.w);
    }
    if (tid < 5) {                                // zero beta pad rows
#pragma unroll
        for (int l = 0; l < 6; l++)
            s_beta[tid * ST + l] = make_float2(0.0f, 0.0f);
    }

    // beta rows for own base (contiguous 24B each, h=0 and h=1)
    const float* pr0 = betas + (size_t)t0 * EDG + eidA[0];
    const float* pr1 = pr0 + MC6;
    float2 a0, a1, a2, b0, b1, b2;
    if (act) {
        a0 = *(const float2*)(pr0 + 0);
        a1 = *(const float2*)(pr0 + 2);
        a2 = *(const float2*)(pr0 + 4);
        b0 = *(const float2*)(pr1 + 0);
        b1 = *(const float2*)(pr1 + 2);
        b2 = *(const float2*)(pr1 + 4);
    }
    float2* gdst = g_v2c[rbuf ^ 1];

    for (int k = 1; k <= KK; k++) {
        // stage current betas; prefetch next iteration's rows
        if (act) {
            float2* br = &s_beta[(s + 5) * ST];
            br[0] = make_float2(a0.x, b0.x);
            br[1] = make_float2(a0.y, b0.y);
            br[2] = make_float2(a1.x, b1.x);
            br[3] = make_float2(a1.y, b1.y);
            br[4] = make_float2(a2.x, b2.x);
            br[5] = make_float2(a2.y, b2.y);
            if (k < KK) {
                pr0 += EDG; pr1 += EDG;
                a0 = *(const float2*)(pr0 + 0);
                a1 = *(const float2*)(pr0 + 2);
                a2 = *(const float2*)(pr0 + 4);
                b0 = *(const float2*)(pr1 + 0);
                b1 = *(const float2*)(pr1 + 2);
                b2 = *(const float2*)(pr1 + 4);
            }
        }
        __syncthreads();

        // ---- check phase: own row (12 edges in-thread), serial top-2 ----
        float2 v[6];
#pragma unroll
        for (int l = 0; l < 6; l++) v[l] = s_msg[s * ST + l];

        float m1 = __int_as_float(0x7f800000), m2 = m1;
        int   e1 = 0x7fffffff;
        unsigned allx = 0u;
#pragma unroll
        for (int l = 0; l < 6; l++) {
            int eA = eidA[l];
            allx ^= __float_as_uint(v[l].x) ^ __float_as_uint(v[l].y);
            {   // h = 0
                float m = fabsf(v[l].x);
                if (m < m1)       { m2 = m1; m1 = m; e1 = eA; }
                else if (m == m1) { m2 = m1; if (eA < e1) e1 = eA; }
                else if (m < m2)  { m2 = m; }
            }
            {   // h = 1
                int eB = eA + MC6;
                float m = fabsf(v[l].y);
                if (m < m1)       { m2 = m1; m1 = m; e1 = eB; }
                else if (m == m1) { m2 = m1; if (eB < e1) e1 = eB; }
                else if (m < m2)  { m2 = m; }
            }
        }
        // outputs: sign of excl-product via parity XOR on bit 31
#pragma unroll
        for (int l = 0; l < 6; l++) {
            float2 bb = s_beta[(s - l + 5) * ST + l];   // diag, conflict-free
            float selA = (eidA[l]       == e1) ? m2 : m1;
            float selB = (eidA[l] + MC6 == e1) ? m2 : m1;
            unsigned fA = (allx ^ __float_as_uint(v[l].x)) & 0x80000000u;
            unsigned fB = (allx ^ __float_as_uint(v[l].y)) & 0x80000000u;
            float oA = __uint_as_float(__float_as_uint(bb.x * selA) ^ fA);
            float oB = __uint_as_float(__float_as_uint(bb.y * selB) ^ fB);
            if (act) s_msg[s * ST + l] = make_float2(oA, oB);  // c2v in place
        }
        __syncthreads();

        // ---- variable phase: diagonal (unique producer/consumer per elem) ----
        bool actv = tid < WW - 5;
        int  x    = actv ? tid : 0;
        float2 cv[6];
        float s0 = 0.0f, s1 = 0.0f;
#pragma unroll
        for (int l = 0; l < 6; l++) {
            cv[l] = s_msg[(x + l) * ST + l];
            s0 += cv[l].x; s1 += cv[l].y;
        }
        float tp0 = llr.x + s0;
        float tp1 = llr.y + s1;

        if (k < KK) {
            if (actv) {
#pragma unroll
                for (int l = 0; l < 6; l++)
                    s_msg[(x + l) * ST + l] =
                        make_float2(tp0 - cv[l].x, tp1 - cv[l].y);
            }
        } else if (tid >= HL && tid < HL + NB) {      // owned writeback
#pragma unroll
            for (int l = 0; l < 6; l++)
                gdst[(int)(((c + (unsigned)l) & MMSK) * 6u + (unsigned)l)] =
                    make_float2(tp0 - cv[l].x, tp1 - cv[l].y);
            g_post[c] = make_float2(tp0, tp1);
        }
        if (tid >= HL - 5 && tid < HL + NB)
            sp[tid - (HL - 5)] =
                (unsigned char)(((tp0 < 0.0f) ? 1 : 0) ^ ((tp1 < 0.0f) ? 1 : 0));
        __syncthreads();

        // ---- syndrome of owned checks at iteration t0+k-1 ----
        int par = 0;
        if (tid < NB)
            par = sp[tid] ^ sp[tid + 1] ^ sp[tid + 2] ^ sp[tid + 3] ^
                  sp[tid + 4] ^ sp[tid + 5];
        int anyodd = __syncthreads_or(par);
        if (anyodd && tid == 0) g_synflag[t0 + k - 1] = 1;   // benign race
    }
}

// ---------------------------------------------------------------------------
__global__ void k_out(float* __restrict__ out, int out_size) {
    unsigned b = blockIdx.x * blockDim.x + threadIdx.x;   // base 0..MC-1
    float2 P = g_post[b];
    unsigned r = (AINV * b) & MMSK;

    if ((int)r < out_size)               out[r]             = (P.x < 0.0f) ? 1.0f : 0.0f;
    if ((int)(r + MCC) < out_size)       out[r + MCC]       = (P.y < 0.0f) ? 1.0f : 0.0f;
    if ((int)(NVV + r) < out_size)       out[NVV + r]       = P.x;
    if ((int)(NVV + r + MCC) < out_size) out[NVV + r + MCC] = P.y;

    if (b == 0 && 2 * NVV < out_size) {
        int iters = TMAXX;
        for (int tt = 0; tt < TMAXX; tt++)
            if (g_synflag[tt] == 0) { iters = tt + 1; break; }
        out[2 * NVV] = (float)iters;
    }
}

// ---------------------------------------------------------------------------
extern "C" void kernel_launch(void* const* d_in, const int* in_sizes, int n_in,
                              void* d_out, int out_size) {
    const float* llr   = (const float*)d_in[0];
    const float* betas = (const float*)d_in[1];
    (void)in_sizes; (void)n_in;

    k_init<<<MCC / 256, 256>>>(llr);
    for (int g = 0; g < NLAUNCH; g++)
        k_fused<<<GRD, THR>>>(betas, g * KK, g & 1);
    k_out<<<MCC / 256, 256>>>((float*)d_out, out_size);
}

// round 11
// speedup vs baseline: 1.7467x; 1.0672x over previous
#include <cuda_runtime.h>
#include <cstdint>

// ---------------------------------------------------------------------------
// NeuralMinSumDecoder — banded Tanner graph (A=48271, A^-1=57967 mod 2^16).
// Base b touches checks b..b+5; check c touches bases c-5..c, halves h=0/1.
// One thread per slot handling BOTH halves as float2. KK=5 iterations fused
// per launch (trapezoid halo). Check phase writes RAW ±sel messages; the
// beta weighting is applied by the variable phase using the thread's OWN
// register-resident beta row (bitwise-identical result). 2 barriers/iter;
// syndrome or-reduce folded into the mid barrier (deferred by one iter).
// ---------------------------------------------------------------------------

#define MCC   65536
#define NVV   131072
#define TMAXX 30
#define EDG   (NVV * 6)
#define MC6   (MCC * 6)
#define AINV  57967u
#define MMSK  0xFFFFu

#define NB    128                 // owned bases/checks per block
#define KK    5                   // iterations per launch
#define HL    (5 * KK + 5)        // 30 (extra 5 for syndrome halo)
#define HR    (5 * KK)            // 25
#define WW    (NB + HL + HR)      // 183 slots
#define THR   192                 // one thread per slot (warp multiple)
#define GRD   (MCC / NB)          // 512 blocks
#define NLAUNCH (TMAXX / KK)      // 6
#define ST    13                  // smem row stride in float2 (conflict-free)

__device__ __align__(16) float2 g_v2c[2][MC6];  // [buf][c*6+l] = (h0,h1)
__device__ float2 g_llr2[MCC];                  // (llr[r], llr[r+M]) by base b
__device__ float2 g_post[MCC];                  // posterior pair by base b
__device__ int    g_synflag[TMAXX];             // 0 => syndrome all-zero at t

// ---------------------------------------------------------------------------
__global__ void k_init(const float* __restrict__ llr) {
    unsigned c = blockIdx.x * blockDim.x + threadIdx.x;   // 0..MC-1
    unsigned r = (AINV * c) & MMSK;
    g_llr2[c] = make_float2(llr[r], llr[r + MCC]);
#pragma unroll
    for (int l = 0; l < 6; l++) {
        unsigned rl = (AINV * (c - (unsigned)l)) & MMSK;
        g_v2c[0][c * 6 + l] = make_float2(llr[rl], llr[rl + MCC]);
    }
    if (c < TMAXX) g_synflag[c] = 0;
}

// ---------------------------------------------------------------------------
__global__ __launch_bounds__(THR, 4) void k_fused(
        const float* __restrict__ betas, int t0, int rbuf) {
    __shared__ float2 s_msg[WW * ST];            // v2c / raw c2v, in place
    __shared__ unsigned char sp[NB + 6];
    int tid = threadIdx.x;

    // frozen check: one flag per thread, boolean or-reduce
    int myf = (tid < t0) ? (g_synflag[tid] == 0) : 0;
    if (__syncthreads_or(myf)) return;

    bool act = tid < WW;
    int  s   = act ? tid : WW - 1;
    unsigned B0 = blockIdx.x * NB;
    unsigned c  = (B0 - (unsigned)HL + (unsigned)s) & MMSK;

    int eidA[6];                          // edge id, h=0 (argmin tiebreak)
#pragma unroll
    for (int l = 0; l < 6; l++) {
        unsigned rl = (AINV * (c - (unsigned)l)) & MMSK;
        eidA[l] = (int)(rl * 6u + (unsigned)l);
    }
    float2 llr = g_llr2[c];

    // load v2c row (3x LDG.128, coalesced) into own smem row
    const float4* gv = (const float4*)&g_v2c[rbuf][c * 6];
    float4 q0 = gv[0], q1 = gv[1], q2 = gv[2];
    if (act) {
        s_msg[s * ST + 0] = make_float2(q0.x, q0.y);
        s_msg[s * ST + 1] = make_float2(q0.z, q0.w);
        s_msg[s * ST + 2] = make_float2(q1.x, q1.y);
        s_msg[s * ST + 3] = make_float2(q1.z, q1.w);
        s_msg[s * ST + 4] = make_float2(q2.x, q2.y);
        s_msg[s * ST + 5] = make_float2(q2.z, q2.w);
    }

    // beta rows for OWN base (contiguous 24B each, h=0 and h=1), iter t0
    const float* pr0 = betas + (size_t)t0 * EDG + eidA[0];
    const float* pr1 = pr0 + MC6;
    float2 ca0, ca1, ca2, cb0, cb1, cb2;        // current iteration's betas
    ca0 = *(const float2*)(pr0 + 0);
    ca1 = *(const float2*)(pr0 + 2);
    ca2 = *(const float2*)(pr0 + 4);
    cb0 = *(const float2*)(pr1 + 0);
    cb1 = *(const float2*)(pr1 + 2);
    cb2 = *(const float2*)(pr1 + 4);
    float2* gdst = g_v2c[rbuf ^ 1];
    __syncthreads();

    for (int k = 1; k <= KK; k++) {
        // prefetch next iteration's betas (overlaps this iteration)
        float2 na0, na1, na2, nb0, nb1, nb2;
        if (k < KK) {
            pr0 += EDG; pr1 += EDG;
            na0 = *(const float2*)(pr0 + 0);
            na1 = *(const float2*)(pr0 + 2);
            na2 = *(const float2*)(pr0 + 4);
            nb0 = *(const float2*)(pr1 + 0);
            nb1 = *(const float2*)(pr1 + 2);
            nb2 = *(const float2*)(pr1 + 4);
        }

        // ---- check phase: own row (12 edges in-thread), serial top-2 ----
        float2 v[6];
#pragma unroll
        for (int l = 0; l < 6; l++) v[l] = s_msg[s * ST + l];

        float m1 = __int_as_float(0x7f800000), m2 = m1;
        int   e1 = 0x7fffffff;
        unsigned allx = 0u;
#pragma unroll
        for (int l = 0; l < 6; l++) {
            int eA = eidA[l];
            allx ^= __float_as_uint(v[l].x) ^ __float_as_uint(v[l].y);
            {   // h = 0
                float m = fabsf(v[l].x);
                if (m < m1)       { m2 = m1; m1 = m; e1 = eA; }
                else if (m == m1) { m2 = m1; if (eA < e1) e1 = eA; }
                else if (m < m2)  { m2 = m; }
            }
            {   // h = 1
                int eB = eA + MC6;
                float m = fabsf(v[l].y);
                if (m < m1)       { m2 = m1; m1 = m; e1 = eB; }
                else if (m == m1) { m2 = m1; if (eB < e1) e1 = eB; }
                else if (m < m2)  { m2 = m; }
            }
        }
        // raw outputs: ±sel (beta applied by the consumer in var phase)
#pragma unroll
        for (int l = 0; l < 6; l++) {
            float selA = (eidA[l]       == e1) ? m2 : m1;
            float selB = (eidA[l] + MC6 == e1) ? m2 : m1;
            unsigned fA = (allx ^ __float_as_uint(v[l].x)) & 0x80000000u;
            unsigned fB = (allx ^ __float_as_uint(v[l].y)) & 0x80000000u;
            float oA = __uint_as_float(__float_as_uint(selA) ^ fA);
            float oB = __uint_as_float(__float_as_uint(selB) ^ fB);
            if (act) s_msg[s * ST + l] = make_float2(oA, oB);
        }

        // ---- mid barrier: publishes raw c2v AND reduces PREVIOUS syndrome --
        int par = 0;
        if (k > 1 && tid < NB)
            par = sp[tid] ^ sp[tid + 1] ^ sp[tid + 2] ^ sp[tid + 3] ^
                  sp[tid + 4] ^ sp[tid + 5];
        int anyodd = __syncthreads_or(par);
        if (k > 1 && anyodd && tid == 0) g_synflag[t0 + k - 2] = 1;

        // ---- variable phase: diagonal reads, own betas in registers ----
        bool actv = tid < WW - 5;
        int  x    = actv ? tid : 0;
        float bx[6] = {ca0.x, ca0.y, ca1.x, ca1.y, ca2.x, ca2.y};
        float by[6] = {cb0.x, cb0.y, cb1.x, cb1.y, cb2.x, cb2.y};
        float2 cv[6];
        float s0 = 0.0f, s1 = 0.0f;
#pragma unroll
        for (int l = 0; l < 6; l++) {
            float2 raw = s_msg[(x + l) * ST + l];
            cv[l] = make_float2(bx[l] * raw.x, by[l] * raw.y);
            s0 += cv[l].x; s1 += cv[l].y;
        }
        float tp0 = llr.x + s0;
        float tp1 = llr.y + s1;

        if (k < KK) {
            if (actv) {
#pragma unroll
                for (int l = 0; l < 6; l++)
                    s_msg[(x + l) * ST + l] =
                        make_float2(tp0 - cv[l].x, tp1 - cv[l].y);
            }
        } else if (tid >= HL && tid < HL + NB) {      // owned writeback
#pragma unroll
            for (int l = 0; l < 6; l++)
                gdst[(int)(((c + (unsigned)l) & MMSK) * 6u + (unsigned)l)] =
                    make_float2(tp0 - cv[l].x, tp1 - cv[l].y);
            g_post[c] = make_float2(tp0, tp1);
        }
        if (tid >= HL - 5 && tid < HL + NB)
            sp[tid - (HL - 5)] =
                (unsigned char)(((tp0 < 0.0f) ? 1 : 0) ^ ((tp1 < 0.0f) ? 1 : 0));
        __syncthreads();                              // end-of-iter barrier

        ca0 = na0; ca1 = na1; ca2 = na2;              // rotate beta buffers
        cb0 = nb0; cb1 = nb1; cb2 = nb2;
    }

    // trailing syndrome reduce for iteration t0+KK-1
    int par = 0;
    if (tid < NB)
        par = sp[tid] ^ sp[tid + 1] ^ sp[tid + 2] ^ sp[tid + 3] ^
              sp[tid + 4] ^ sp[tid + 5];
    int anyodd = __syncthreads_or(par);
    if (anyodd && tid == 0) g_synflag[t0 + KK - 1] = 1;   // benign race
}

// ---------------------------------------------------------------------------
__global__ void k_out(float* __restrict__ out, int out_size) {
    unsigned b = blockIdx.x * blockDim.x + threadIdx.x;   // base 0..MC-1
    float2 P = g_post[b];
    unsigned r = (AINV * b) & MMSK;

    if ((int)r < out_size)               out[r]             = (P.x < 0.0f) ? 1.0f : 0.0f;
    if ((int)(r + MCC) < out_size)       out[r + MCC]       = (P.y < 0.0f) ? 1.0f : 0.0f;
    if ((int)(NVV + r) < out_size)       out[NVV + r]       = P.x;
    if ((int)(NVV + r + MCC) < out_size) out[NVV + r + MCC] = P.y;

    if (b == 0 && 2 * NVV < out_size) {
        int iters = TMAXX;
        for (int tt = 0; tt < TMAXX; tt++)
            if (g_synflag[tt] == 0) { iters = tt + 1; break; }
        out[2 * NVV] = (float)iters;
    }
}

// ---------------------------------------------------------------------------
extern "C" void kernel_launch(void* const* d_in, const int* in_sizes, int n_in,
                              void* d_out, int out_size) {
    const float* llr   = (const float*)d_in[0];
    const float* betas = (const float*)d_in[1];
    (void)in_sizes; (void)n_in;

    k_init<<<MCC / 256, 256>>>(llr);
    for (int g = 0; g < NLAUNCH; g++)
        k_fused<<<GRD, THR>>>(betas, g * KK, g & 1);
    k_out<<<MCC / 256, 256>>>((float*)d_out, out_size);
}